// round 1
// baseline (speedup 1.0000x reference)
#include <cuda_runtime.h>
#include <cuda_bf16.h>

#define MAX_ATOMS 500000
#define MAX_MOL   5000

// Scratch (allocation-free: __device__ globals)
__device__ float g_qm[MAX_MOL];     // per-molecule charge sum
__device__ float g_qc[MAX_ATOMS];   // corrected charge * 1/sqrt(2)

// ---------------------------------------------------------------------------
// Kernel 1: per-molecule charge sums. atom_mol_batch is sorted blocks of 100,
// and 4 | 100, so a 4-aligned group almost never straddles molecules -> one
// atomic per 4 atoms in the common case.
// ---------------------------------------------------------------------------
__global__ __launch_bounds__(256)
void k_qmol(const float* __restrict__ qi, const int* __restrict__ batch, int n_atoms)
{
    int i = (blockIdx.x * blockDim.x + threadIdx.x) * 4;
    if (i + 3 < n_atoms) {
        float4 q = *(const float4*)(qi + i);
        int4   b = *(const int4*)(batch + i);
        if (b.x == b.w) {
            atomicAdd(&g_qm[b.x], q.x + q.y + q.z + q.w);
        } else {
            atomicAdd(&g_qm[b.x], q.x);
            atomicAdd(&g_qm[b.y], q.y);
            atomicAdd(&g_qm[b.z], q.z);
            atomicAdd(&g_qm[b.w], q.w);
        }
    } else {
        for (; i < n_atoms; i++) atomicAdd(&g_qm[batch[i]], qi[i]);
    }
}

// ---------------------------------------------------------------------------
// Kernel 2: corrected, pre-scaled charges:
//   qc[a] = (qi[a] - (q_mol[m]-q_ref[m])/N[m]) * (1/sqrt(2))
// The 1/sqrt(2) makes qc[i]*qc[j] carry the global /2 for double counting.
// ---------------------------------------------------------------------------
__global__ __launch_bounds__(256)
void k_correct(const float* __restrict__ qi, const int* __restrict__ batch,
               const float* __restrict__ q_ref, const int* __restrict__ Nmol,
               int n_atoms)
{
    const float s = 0.70710678118654752440f;
    int i = (blockIdx.x * blockDim.x + threadIdx.x) * 4;
    if (i + 3 < n_atoms) {
        float4 q = *(const float4*)(qi + i);
        int4   b = *(const int4*)(batch + i);
        float4 o;
        {
            float corr = (g_qm[b.x] - __ldg(&q_ref[b.x])) / (float)__ldg(&Nmol[b.x]);
            o.x = (q.x - corr) * s;
        }
        {
            float corr = (g_qm[b.y] - __ldg(&q_ref[b.y])) / (float)__ldg(&Nmol[b.y]);
            o.y = (q.y - corr) * s;
        }
        {
            float corr = (g_qm[b.z] - __ldg(&q_ref[b.z])) / (float)__ldg(&Nmol[b.z]);
            o.z = (q.z - corr) * s;
        }
        {
            float corr = (g_qm[b.w] - __ldg(&q_ref[b.w])) / (float)__ldg(&Nmol[b.w]);
            o.w = (q.w - corr) * s;
        }
        *(float4*)(g_qc + i) = o;
    } else {
        for (; i < n_atoms; i++) {
            int m = batch[i];
            float corr = (g_qm[m] - q_ref[m]) / (float)Nmol[m];
            g_qc[i] = (qi[i] - corr) * s;
        }
    }
}

// ---------------------------------------------------------------------------
// chi(r) = f(2r)*phi + (1-f(2r))/r ; f is PhysNet smooth cutoff with cutoff=10
// => x = 2r/10 = r/5
// ---------------------------------------------------------------------------
__device__ __forceinline__ float chi_ij(float r)
{
    float phi = rsqrtf(fmaf(r, r, 1.0f));
    float x   = r * 0.2f;
    float f   = 0.0f;
    if (x < 1.0f) {
        float x2 = x * x;
        float x3 = x2 * x;
        // 1 - 10x^3 + 15x^4 - 6x^5 = 1 - x^3*(10 - 15x + 6x^2)
        f = 1.0f - x3 * fmaf(x, fmaf(6.0f, x, -15.0f), 10.0f);
    }
    float inv_r = __fdividef(1.0f, r);
    return fmaf(f, phi, (1.0f - f) * inv_r);
}

// ---------------------------------------------------------------------------
// Kernel 3 (hot): per-edge. Accumulate S[src] += qc[dst]*chi(r).
// Only ONE random gather per edge (qc[dst]); qc[src] is applied in epilogue.
// ---------------------------------------------------------------------------
__global__ __launch_bounds__(256)
void k_edges(const float* __restrict__ dist,
             const int*   __restrict__ src,
             const int*   __restrict__ dst,
             float*       __restrict__ S,
             int n_edges)
{
    int i = (blockIdx.x * blockDim.x + threadIdx.x) * 4;
    if (i + 3 < n_edges) {
        float4 r4 = __ldg((const float4*)(dist + i));
        int4   s4 = __ldg((const int4*)(src + i));
        int4   d4 = __ldg((const int4*)(dst + i));
        float t0 = __ldg(&g_qc[d4.x]) * chi_ij(r4.x);
        float t1 = __ldg(&g_qc[d4.y]) * chi_ij(r4.y);
        float t2 = __ldg(&g_qc[d4.z]) * chi_ij(r4.z);
        float t3 = __ldg(&g_qc[d4.w]) * chi_ij(r4.w);
        atomicAdd(&S[s4.x], t0);
        atomicAdd(&S[s4.y], t1);
        atomicAdd(&S[s4.z], t2);
        atomicAdd(&S[s4.w], t3);
    } else {
        for (; i < n_edges; i++) {
            float t = __ldg(&g_qc[dst[i]]) * chi_ij(dist[i]);
            atomicAdd(&S[src[i]], t);
        }
    }
}

// ---------------------------------------------------------------------------
// Kernel 4: epilogue  out[a] = qc[a] * S[a]
// (qc carries 1/sqrt(2); S carries 1/sqrt(2) per term -> global 1/2 factor)
// ---------------------------------------------------------------------------
__global__ __launch_bounds__(256)
void k_final(float* __restrict__ out, int n_atoms)
{
    int i = (blockIdx.x * blockDim.x + threadIdx.x) * 4;
    if (i + 3 < n_atoms) {
        float4 s = *(const float4*)(out + i);
        float4 q = *(const float4*)(g_qc + i);
        s.x *= q.x; s.y *= q.y; s.z *= q.z; s.w *= q.w;
        *(float4*)(out + i) = s;
    } else {
        for (; i < n_atoms; i++) out[i] *= g_qc[i];
    }
}

// ---------------------------------------------------------------------------
// Inputs (metadata order):
//  0: qi              float32 [n_atoms]
//  1: edge_dist       float32 [n_edges]
//  2: edge_index      int32   [2, n_edges]
//  3: q_ref           float32 [n_mol]
//  4: N               int32   [n_mol]
//  5: atom_mol_batch  int32   [n_atoms]
// out: float32 [n_atoms]
// ---------------------------------------------------------------------------
extern "C" void kernel_launch(void* const* d_in, const int* in_sizes, int n_in,
                              void* d_out, int out_size)
{
    const float* qi    = (const float*)d_in[0];
    const float* dist  = (const float*)d_in[1];
    const int*   eidx  = (const int*)d_in[2];
    const float* q_ref = (const float*)d_in[3];
    const int*   Nmol  = (const int*)d_in[4];
    const int*   batch = (const int*)d_in[5];
    float* out = (float*)d_out;

    int n_atoms = in_sizes[0];
    int n_edges = in_sizes[2] / 2;
    int n_mol   = in_sizes[3];

    const int* src = eidx;
    const int* dst = eidx + n_edges;

    void* qm_ptr = nullptr;
    cudaGetSymbolAddress(&qm_ptr, g_qm);

    // zero the molecule sums and the S accumulator (d_out is poisoned)
    cudaMemsetAsync(qm_ptr, 0, n_mol * sizeof(float));
    cudaMemsetAsync(out, 0, (size_t)out_size * sizeof(float));

    const int T = 256;
    int blocks_atoms = (n_atoms / 4 + T - 1) / T + 1;   // +1 covers tail
    int blocks_edges = (n_edges / 4 + T - 1) / T + 1;

    k_qmol<<<blocks_atoms, T>>>(qi, batch, n_atoms);
    k_correct<<<blocks_atoms, T>>>(qi, batch, q_ref, Nmol, n_atoms);
    k_edges<<<blocks_edges, T>>>(dist, src, dst, out, n_edges);
    k_final<<<blocks_atoms, T>>>(out, n_atoms);
}